// round 15
// baseline (speedup 1.0000x reference)
#include <cuda_runtime.h>
#include <cuda_fp16.h>
#include <math.h>
#include <stdint.h>

#define DIMV 768
#define NLV 12
#define DSV 16
#define DIV 1536
#define TOKV 8192      // 32 batches * 256 tokens
#define LV 256
#define GSV 5
#define KANK (DIMV * GSV)       // 3840
#define KCAT (KANK + DIMV)      // 4608  (basis | h concat)

// ---------------- scratch (static device globals; no allocation allowed) ----
__device__ float g_h[TOKV * DIMV];                   // running hidden state (fp32)
__device__ float g_Ad[TOKV * DSV];
__device__ float g_Bd[TOKV * DSV];
__device__ float g_ys[TOKV * DSV];
// fp16 activation buffers
__device__ __half g_ah[(size_t)TOKV * KCAT];         // im2col / yg / basis+h concat
__device__ __half g_bh[TOKV * DIMV];                 // h fp16 (GEMM A) — no aliasing
__device__ __half g_xrh[(size_t)TOKV * 2 * DIV];     // in_proj output fp16 (x1|res)
__device__ __half g_x1h[(size_t)TOKV * DIV];         // post conv+silu fp16
// fp16 weight staging
__device__ __half g_wi[(size_t)NLV * 2 * DIV * DIMV];
__device__ __half g_wo[(size_t)NLV * DIMV * DIV];
__device__ __half g_wp[DIMV * DIMV];
__device__ __half g_wkc[(size_t)DIMV * KCAT];        // [wkan | kbw] combined

// ---------------- PTX helpers ----------------------------------------------
__device__ __forceinline__ uint32_t smem_u32(const void* p) {
    uint32_t a;
    asm("{ .reg .u64 t; cvta.to.shared.u64 t, %1; cvt.u32.u64 %0, t; }"
        : "=r"(a) : "l"(p));
    return a;
}
__device__ __forceinline__ void ldsm4(uint32_t& r0, uint32_t& r1,
                                      uint32_t& r2, uint32_t& r3, uint32_t addr)
{
    asm volatile("ldmatrix.sync.aligned.m8n8.x4.shared.b16 {%0,%1,%2,%3}, [%4];"
                 : "=r"(r0), "=r"(r1), "=r"(r2), "=r"(r3) : "r"(addr));
}
__device__ __forceinline__ void mma_f16(float* c, const uint32_t* a, const uint32_t* b)
{
    asm volatile(
        "mma.sync.aligned.m16n8k16.row.col.f32.f16.f16.f32 "
        "{%0,%1,%2,%3}, {%4,%5,%6,%7}, {%8,%9}, {%0,%1,%2,%3};"
        : "+f"(c[0]), "+f"(c[1]), "+f"(c[2]), "+f"(c[3])
        : "r"(a[0]), "r"(a[1]), "r"(a[2]), "r"(a[3]), "r"(b[0]), "r"(b[1]));
}
__device__ __forceinline__ void cp16(uint32_t dst, const void* src)
{
    asm volatile("cp.async.cg.shared.global [%0], [%1], 16;"
                 :: "r"(dst), "l"(src) : "memory");
}
__device__ __forceinline__ void cp_commit()
{
    asm volatile("cp.async.commit_group;" ::: "memory");
}
template<int NN> __device__ __forceinline__ void cp_wait()
{
    asm volatile("cp.async.wait_group %0;" :: "n"(NN) : "memory");
}
__device__ __forceinline__ float h2f(__half h) { return __half2float(h); }

// ---------------- tensor-core GEMM (fp16 single-term mma.sync) --------------
// C[M,N] = A[M,K] @ W[N,K]^T, fp16 operands, fp32 accumulate.
// 128 threads, 4 warps 2x2, warp tile 64x64, CTA tile 128x128, BK=32 fp16,
// 2-stage cp.async, 80B-pitch conflict-free ldmatrix tiles.
// OUT16: fp16 only to Sh. SPLIT: fp16 copy to Sh. HADD: out += H -> H.
#define TILE_B (128 * 80)            // 10240
#define STAGE_B (2 * TILE_B)         // A|W = 20480
#define SMEMT (2 * STAGE_B)          // 40960

template<bool BIAS, bool ACC, bool SPLIT, bool HADD, bool OUT16>
__global__ __launch_bounds__(128, 2)
void tgemm(const __half* __restrict__ A, const __half* __restrict__ W,
           const float* __restrict__ bias, float* __restrict__ C,
           __half* __restrict__ Sh, float* __restrict__ H,
           int M, int N, int K)
{
    extern __shared__ char smem[];
    const uint32_t sb0 = smem_u32(smem);
    const int tid = threadIdx.x, lane = tid & 31, wid = tid >> 5;
    const int row0 = blockIdx.y * 128, col0 = blockIdx.x * 128;
    const int rm = (wid >> 1) * 64, cn = (wid & 1) * 64;

    const __half* gA = A + (size_t)row0 * K;
    const __half* gW = W + (size_t)col0 * K;

    const int lrow = tid >> 2;          // 0..31
    const int lch  = tid & 3;           // 16B chunk 0..3 (8 fp16 each)

    auto issue = [&](int p, int s) {
        const int k0 = p * 32;
        const uint32_t dstb = sb0 + s * STAGE_B;
#pragma unroll
        for (int i = 0; i < 4; i++) {
            int row = lrow + i * 32;
            cp16(dstb + row * 80 + lch * 16,
                 gA + (size_t)row * K + k0 + lch * 8);
        }
#pragma unroll
        for (int i = 0; i < 4; i++) {
            int row = lrow + i * 32;
            cp16(dstb + TILE_B + row * 80 + lch * 16,
                 gW + (size_t)row * K + k0 + lch * 8);
        }
        cp_commit();
    };

    float acc[4][8][4];
#pragma unroll
    for (int a = 0; a < 4; a++)
#pragma unroll
        for (int b = 0; b < 8; b++)
#pragma unroll
            for (int q = 0; q < 4; q++) acc[a][b][q] = 0.f;

    const uint32_t aOff = (uint32_t)(rm + (lane & 15)) * 80 + ((lane >> 4) << 4);
    const uint32_t wOff = (uint32_t)(cn + (lane & 7) + ((lane >> 4) & 1) * 8) * 80
                        + (((lane >> 3) & 1) << 4);

    const int npan = K >> 5;
    issue(0, 0);

    for (int p = 0; p < npan; p++) {
        const bool more = (p + 1 < npan);
        if (more) issue(p + 1, (p + 1) & 1);
        if (more) cp_wait<1>(); else cp_wait<0>();
        __syncthreads();

        const uint32_t sbase = sb0 + (p & 1) * STAGE_B;
#pragma unroll
        for (int ks = 0; ks < 2; ks++) {
            const uint32_t kb = ks * 32;          // 16 fp16 = 32 B
            uint32_t Af[4][4], Wf[8][2];
#pragma unroll
            for (int mt = 0; mt < 4; mt++)
                ldsm4(Af[mt][0], Af[mt][1], Af[mt][2], Af[mt][3],
                      sbase + aOff + mt * 1280 + kb);
#pragma unroll
            for (int bt = 0; bt < 4; bt++) {
                uint32_t r0, r1, r2, r3;
                ldsm4(r0, r1, r2, r3,
                      sbase + TILE_B + wOff + bt * 1280 + kb);
                Wf[bt * 2][0] = r0; Wf[bt * 2][1] = r1;
                Wf[bt * 2 + 1][0] = r2; Wf[bt * 2 + 1][1] = r3;
            }
#pragma unroll
            for (int mt = 0; mt < 4; mt++)
#pragma unroll
                for (int nt = 0; nt < 8; nt++)
                    mma_f16(acc[mt][nt], Af[mt], Wf[nt]);
        }
        __syncthreads();
    }

    // epilogue
#pragma unroll
    for (int mt = 0; mt < 4; mt++) {
#pragma unroll
        for (int nt = 0; nt < 8; nt++) {
            int r = row0 + rm + mt * 16 + (lane >> 2);
            int c = col0 + cn + nt * 8 + (lane & 3) * 2;
            float bx = 0.f, by = 0.f;
            if (BIAS) { bx = bias[c]; by = bias[c + 1]; }
#pragma unroll
            for (int half = 0; half < 2; half++) {
                size_t off = (size_t)(r + half * 8) * N + c;
                float vx = acc[mt][nt][half * 2 + 0] + bx;
                float vy = acc[mt][nt][half * 2 + 1] + by;
                if (OUT16) {
                    *reinterpret_cast<__half2*>(Sh + off) =
                        __floats2half2_rn(vx, vy);
                } else {
                    if (ACC) { vx += C[off]; vy += C[off + 1]; }
                    if (HADD) {
                        vx += H[off]; vy += H[off + 1];
                        *reinterpret_cast<float2*>(H + off) = make_float2(vx, vy);
                    } else {
                        *reinterpret_cast<float2*>(C + off) = make_float2(vx, vy);
                    }
                    if (SPLIT) {
                        *reinterpret_cast<__half2*>(Sh + off) =
                            __floats2half2_rn(vx, vy);
                    }
                }
            }
        }
    }
}

// ---------------- elementwise / small kernels ------------------------------

__global__ void wcvt_k(const float* __restrict__ src, __half* __restrict__ dst, int n4)
{
    int idx = blockIdx.x * blockDim.x + threadIdx.x;
    if (idx >= n4) return;
    float4 v = reinterpret_cast<const float4*>(src)[idx];
    reinterpret_cast<__half2*>(dst)[idx * 2 + 0] = __floats2half2_rn(v.x, v.y);
    reinterpret_cast<__half2*>(dst)[idx * 2 + 1] = __floats2half2_rn(v.z, v.w);
}

__global__ void im2col_k(const float* __restrict__ x)
{
    int idx = blockIdx.x * blockDim.x + threadIdx.x;    // over TOKV*DIMV/4
    if (idx >= TOKV * DIMV / 4) return;
    int col4 = (idx % (DIMV / 4)) * 4;
    int row  = idx / (DIMV / 4);
    int b = row >> 8, t = row & 255;
    int py = t >> 4, px = t & 15;
    int c = col4 >> 8, rj = col4 & 255;
    int r = rj >> 4, s = rj & 15;
    const float4 v = *reinterpret_cast<const float4*>(
        x + (((size_t)(b * 3 + c) * 256) + py * 16 + r) * 256 + px * 16 + s);
    reinterpret_cast<__half2*>(g_ah)[idx * 2 + 0] = __floats2half2_rn(v.x, v.y);
    reinterpret_cast<__half2*>(g_ah)[idx * 2 + 1] = __floats2half2_rn(v.z, v.w);
}

__global__ void addpos_k(const float* __restrict__ pos)
{
    int idx = blockIdx.x * blockDim.x + threadIdx.x;    // over TOKV*DIMV/4
    if (idx >= TOKV * DIMV / 4) return;
    int d4  = idx % (DIMV / 4);
    int row = idx / (DIMV / 4);
    float4 h = reinterpret_cast<const float4*>(g_h)[idx];
    float4 p = reinterpret_cast<const float4*>(pos)[(row & 255) * (DIMV / 4) + d4];
    h.x += p.x; h.y += p.y; h.z += p.z; h.w += p.w;
    reinterpret_cast<float4*>(g_h)[idx] = h;
    reinterpret_cast<__half2*>(g_bh)[idx * 2 + 0] = __floats2half2_rn(h.x, h.y);
    reinterpret_cast<__half2*>(g_bh)[idx * 2 + 1] = __floats2half2_rn(h.z, h.w);
}

// FUSED: depthwise causal conv(4)+silu  +  dt/Bp projection + softplus/Ad/Bd.
// Block = 64 token-rows. During tile load, x1 is computed from g_xrh and
// written once to g_x1h (for yg) and to smem for the projection.
__global__ __launch_bounds__(256)
void dtbp_k(const float* __restrict__ cw, const float* __restrict__ cb,
            const float* __restrict__ dtw, const float* __restrict__ dtb,
            const float* __restrict__ xpw, const float* __restrict__ alog)
{
    __shared__ float Xs[64][36];
    __shared__ float Ws2[32][33];

    const int tid = threadIdx.x;
    const int lane = tid & 31;
    const int wid = tid >> 5;
    const int row0 = blockIdx.x * 64;

    const int xrow = tid >> 3;          // 0..31
    const int xk4  = (tid & 7) * 4;

    float acc[8];
#pragma unroll
    for (int r = 0; r < 8; r++) acc[r] = 0.f;

    const float* wsrc = (xrow < 16)
        ? (dtw + (size_t)xrow * DIV)
        : (xpw + (size_t)xrow * DIV);

    for (int kt = 0; kt < DIV; kt += 32) {
        const int c0 = kt + xk4;
        float4 cbv = *reinterpret_cast<const float4*>(cb + c0);
        float4 cw0 = *reinterpret_cast<const float4*>(cw + (c0 + 0) * 4);
        float4 cw1 = *reinterpret_cast<const float4*>(cw + (c0 + 1) * 4);
        float4 cw2 = *reinterpret_cast<const float4*>(cw + (c0 + 2) * 4);
        float4 cw3 = *reinterpret_cast<const float4*>(cw + (c0 + 3) * 4);
        const float* w0 = (const float*)&cw0;
        const float* w1 = (const float*)&cw1;
        const float* w2 = (const float*)&cw2;
        const float* w3 = (const float*)&cw3;

#pragma unroll
        for (int hf = 0; hf < 2; hf++) {
            int row = row0 + hf * 32 + xrow;
            int l = row & 255;
            float a0 = cbv.x, a1 = cbv.y, a2 = cbv.z, a3 = cbv.w;
#pragma unroll
            for (int k = 0; k < 4; k++) {
                if (l - 3 + k >= 0) {
                    const __half2* xp = reinterpret_cast<const __half2*>(
                        g_xrh + (size_t)(row - 3 + k) * (2 * DIV) + c0);
                    float2 p01 = __half22float2(xp[0]);
                    float2 p23 = __half22float2(xp[1]);
                    a0 = fmaf(p01.x, w0[k], a0);
                    a1 = fmaf(p01.y, w1[k], a1);
                    a2 = fmaf(p23.x, w2[k], a2);
                    a3 = fmaf(p23.y, w3[k], a3);
                }
            }
            a0 = a0 / (1.f + expf(-a0));
            a1 = a1 / (1.f + expf(-a1));
            a2 = a2 / (1.f + expf(-a2));
            a3 = a3 / (1.f + expf(-a3));
            float* xs = &Xs[hf * 32 + xrow][xk4];
            xs[0] = a0; xs[1] = a1; xs[2] = a2; xs[3] = a3;
            __half2* dst = reinterpret_cast<__half2*>(g_x1h + (size_t)row * DIV + c0);
            dst[0] = __floats2half2_rn(a0, a1);
            dst[1] = __floats2half2_rn(a2, a3);
        }

        float4 wv = *reinterpret_cast<const float4*>(wsrc + kt + xk4);
        Ws2[xrow][xk4 + 0] = wv.x; Ws2[xrow][xk4 + 1] = wv.y;
        Ws2[xrow][xk4 + 2] = wv.z; Ws2[xrow][xk4 + 3] = wv.w;
        __syncthreads();
#pragma unroll
        for (int kk = 0; kk < 32; kk++) {
            float w = Ws2[lane][kk];
#pragma unroll
            for (int r = 0; r < 8; r++)
                acc[r] = fmaf(Xs[wid * 8 + r][kk], w, acc[r]);
        }
        __syncthreads();
    }

    float dtb_v = (lane < DSV) ? dtb[lane] : 0.f;
    float negA  = (lane < DSV) ? -expf(alog[lane]) : 0.f;

#pragma unroll
    for (int r = 0; r < 8; r++) {
        int row = row0 + wid * 8 + r;
        const __half* xr = g_x1h + (size_t)row * DIV;
        float s = h2f(xr[lane]) + h2f(xr[lane + 32]) + h2f(xr[lane + 64]);
#pragma unroll
        for (int o = 16; o; o >>= 1) s += __shfl_xor_sync(0xffffffffu, s, o);
        float u = s * (1.f / 96.f);
        float bp = __shfl_sync(0xffffffffu, acc[r], (lane & 15) + 16);
        if (lane < DSV) {
            float raw = acc[r] + dtb_v;
            float dtv = fmaxf(raw, 0.f) + log1pf(expf(-fabsf(raw)));
            g_Ad[row * DSV + lane] = expf(negA * dtv);
            g_Bd[row * DSV + lane] = dtv * bp * u;
        }
    }
}

// warp-parallel linear-recurrence scan
__global__ void scan_k()   // <<<64, 256>>> : 512 warps
{
    int g = blockIdx.x * blockDim.x + threadIdx.x;
    int w = g >> 5, lane = g & 31;
    int b = w >> 4, n = w & 15;
    size_t idx0 = (size_t)b * LV * DSV + n + (size_t)(lane * 8) * DSV;

    float a[8], bb[8];
    float A = 1.f, B = 0.f;
#pragma unroll
    for (int i = 0; i < 8; i++) {
        a[i]  = g_Ad[idx0 + (size_t)i * DSV];
        bb[i] = g_Bd[idx0 + (size_t)i * DSV];
        B = B * a[i] + bb[i];
        A = A * a[i];
    }
    float Ai = A, Bi = B;
#pragma unroll
    for (int o = 1; o < 32; o <<= 1) {
        float Ap = __shfl_up_sync(0xffffffffu, Ai, o);
        float Bp = __shfl_up_sync(0xffffffffu, Bi, o);
        if (lane >= o) { Bi = Bp * Ai + Bi; Ai = Ai * Ap; }
    }
    float sin = __shfl_up_sync(0xffffffffu, Bi, 1);
    if (lane == 0) sin = 0.f;
    float s = sin;
#pragma unroll
    for (int i = 0; i < 8; i++) {
        s = s * a[i] + bb[i];
        g_ys[idx0 + (size_t)i * DSV] = s;
    }
}

// gated y -> fp16 into g_ah ([8192,1536] pitch DIV)
__global__ void yg_k(const float* __restrict__ Dp)
{
    int idx = blockIdx.x * blockDim.x + threadIdx.x;    // over TOKV*DIV/4
    if (idx >= TOKV * DIV / 4) return;
    int c4  = (idx % (DIV / 4)) * 4;
    int row = idx / (DIV / 4);
    float ys = g_ys[row * DSV + c4 / 96];
    const __half2* x1p = reinterpret_cast<const __half2*>(g_x1h) + idx * 2;
    float2 x01 = __half22float2(x1p[0]), x23 = __half22float2(x1p[1]);
    float4 dp = *reinterpret_cast<const float4*>(Dp + c4);
    const __half2* rsp = reinterpret_cast<const __half2*>(
        g_xrh + (size_t)row * (2 * DIV) + DIV + c4);
    float2 r01 = __half22float2(rsp[0]), r23 = __half22float2(rsp[1]);
    float ox = (ys + x01.x * dp.x) * (r01.x / (1.f + expf(-r01.x)));
    float oy = (ys + x01.y * dp.y) * (r01.y / (1.f + expf(-r01.y)));
    float oz = (ys + x23.x * dp.z) * (r23.x / (1.f + expf(-r23.x)));
    float ow = (ys + x23.y * dp.w) * (r23.y / (1.f + expf(-r23.y)));
    reinterpret_cast<__half2*>(g_ah)[idx * 2 + 0] = __floats2half2_rn(ox, oy);
    reinterpret_cast<__half2*>(g_ah)[idx * 2 + 1] = __floats2half2_rn(oz, ow);
}

// combined KAN weight: W row o = [ wkan(o, c=ii*5+k) | kbw(o, :) ], K = 4608
__global__ void repack2_k(const float* __restrict__ coeff, const float* __restrict__ kbw)
{
    int idx = blockIdx.x * blockDim.x + threadIdx.x;
    const int TOTAL = DIMV * KCAT;
    if (idx >= TOTAL) return;
    int o = idx / KCAT;
    int c = idx % KCAT;
    float v;
    if (c < KANK)
        v = coeff[((size_t)o * DIMV + c / GSV) * 8 + c % GSV];
    else
        v = kbw[(size_t)o * DIMV + (c - KANK)];
    g_wkc[idx] = __float2half_rn(v);
}

// KAN A build: row = [basis(3840) | h(768)] fp16, pitch KCAT
__global__ void kanA_k()
{
    int idx = blockIdx.x * blockDim.x + threadIdx.x;    // over TOKV*DIMV/4
    if (idx >= TOKV * DIMV / 4) return;
    int d4  = (idx % (DIMV / 4)) * 4;
    int row = idx / (DIMV / 4);
    float4 h = reinterpret_cast<const float4*>(g_h)[idx];
    const float* hv = (const float*)&h;
    size_t rbase = (size_t)row * KCAT;
    __half tmp[20];
    const float inv = 1.f / (0.4f + 1e-8f);
#pragma unroll
    for (int e = 0; e < 4; e++) {
        float xv = hv[e];
#pragma unroll
        for (int k = 0; k < GSV; k++) {
            float gk = -1.f + 0.4f * (float)k;
            float xs = (xv - gk) * inv;
            float v = (xs >= 0.f && xs < 1.f) ? xs : 0.f;
            tmp[e * GSV + k] = __float2half_rn(v);
        }
    }
    // basis: 20 halves at rbase + d4*5 (8B aligned)
    uint2* bd = reinterpret_cast<uint2*>(g_ah + rbase + (size_t)d4 * 5);
    const uint2* ts = reinterpret_cast<const uint2*>(tmp);
#pragma unroll
    for (int q = 0; q < 5; q++) bd[q] = ts[q];
    // h tail: 4 halves at rbase + KANK + d4
    __half2* hd = reinterpret_cast<__half2*>(g_ah + rbase + KANK + d4);
    hd[0] = __floats2half2_rn(h.x, h.y);
    hd[1] = __floats2half2_rn(h.z, h.w);
}

__global__ void ln_k(const float* __restrict__ nw, const float* __restrict__ nb,
                     float* __restrict__ out)
{
    __shared__ float sh[DIMV];
    __shared__ float sbuf[8];
    int row = blockIdx.x;
    int tid = threadIdx.x;
    int lane = tid & 31, w = tid >> 5;

    float s = 0.f;
    for (int d = tid; d < DIMV; d += 256) {
        float v = g_h[(size_t)row * DIMV + d];
        sh[d] = v; s += v;
    }
#pragma unroll
    for (int o = 16; o; o >>= 1) s += __shfl_xor_sync(0xffffffffu, s, o);
    if (lane == 0) sbuf[w] = s;
    __syncthreads();
    if (w == 0) {
        float t = (lane < 8) ? sbuf[lane] : 0.f;
#pragma unroll
        for (int o = 4; o; o >>= 1) t += __shfl_xor_sync(0xffffffffu, t, o);
        if (lane == 0) sbuf[0] = t;
    }
    __syncthreads();
    float mu = sbuf[0] * (1.f / DIMV);
    __syncthreads();

    float s2 = 0.f;
    for (int d = tid; d < DIMV; d += 256) {
        float dv = sh[d] - mu;
        s2 += dv * dv;
    }
#pragma unroll
    for (int o = 16; o; o >>= 1) s2 += __shfl_xor_sync(0xffffffffu, s2, o);
    if (lane == 0) sbuf[w] = s2;
    __syncthreads();
    if (w == 0) {
        float t = (lane < 8) ? sbuf[lane] : 0.f;
#pragma unroll
        for (int o = 4; o; o >>= 1) t += __shfl_xor_sync(0xffffffffu, t, o);
        if (lane == 0) sbuf[0] = t;
    }
    __syncthreads();
    float var = sbuf[0] * (1.f / DIMV);
    float inv = rsqrtf(var + 1e-5f);
    for (int d = tid; d < DIMV; d += 256) {
        out[(size_t)row * DIMV + d] = (sh[d] - mu) * inv * nw[d] + nb[d];
    }
}

// ---------------- host orchestration ---------------------------------------

extern "C" void kernel_launch(void* const* d_in, const int* in_sizes, int n_in,
                              void* d_out, int out_size)
{
    const float* x       = (const float*)d_in[0];
    const float* patch_w = (const float*)d_in[1];
    const float* patch_b = (const float*)d_in[2];
    const float* pos     = (const float*)d_in[3];
    const float* in_w    = (const float*)d_in[4];
    const float* conv_w  = (const float*)d_in[5];
    const float* conv_b  = (const float*)d_in[6];
    const float* xpw     = (const float*)d_in[7];
    const float* dtw     = (const float*)d_in[8];
    const float* dtb     = (const float*)d_in[9];
    const float* alog    = (const float*)d_in[10];
    const float* Dp      = (const float*)d_in[11];
    const float* ow      = (const float*)d_in[12];
    const float* kbw     = (const float*)d_in[13];
    const float* kco     = (const float*)d_in[14];
    const float* kbi     = (const float*)d_in[15];
    const float* nw      = (const float*)d_in[16];
    const float* nb      = (const float*)d_in[17];
    float* out = (float*)d_out;

    cudaFuncSetAttribute(tgemm<false, false, false, false, true >, cudaFuncAttributeMaxDynamicSharedMemorySize, SMEMT);
    cudaFuncSetAttribute(tgemm<false, false, true,  false, false>, cudaFuncAttributeMaxDynamicSharedMemorySize, SMEMT);
    cudaFuncSetAttribute(tgemm<true,  false, false, false, false>, cudaFuncAttributeMaxDynamicSharedMemorySize, SMEMT);
    cudaFuncSetAttribute(tgemm<true,  false, true,  true,  false>, cudaFuncAttributeMaxDynamicSharedMemorySize, SMEMT);

    float *p_h;
    __half *p_ah, *p_bh, *p_xrh, *p_wi, *p_wo, *p_wp, *p_wkc;
    cudaGetSymbolAddress((void**)&p_h,   g_h);
    cudaGetSymbolAddress((void**)&p_ah,  g_ah);
    cudaGetSymbolAddress((void**)&p_bh,  g_bh);
    cudaGetSymbolAddress((void**)&p_xrh, g_xrh);
    cudaGetSymbolAddress((void**)&p_wi,  g_wi);
    cudaGetSymbolAddress((void**)&p_wo,  g_wo);
    cudaGetSymbolAddress((void**)&p_wp,  g_wp);
    cudaGetSymbolAddress((void**)&p_wkc, g_wkc);

    const int T = 256;
    const int GT = 128;          // tgemm threads
    const int MB = TOKV / 128;   // 64
    const int EW4 = (TOKV * DIMV / 4 + T - 1) / T;
    const int EX4 = (TOKV * DIV / 4 + T - 1) / T;

    // ---- weight fp16 conversion ----
    {
        int n4;
        n4 = NLV * 2 * DIV * DIMV / 4;
        wcvt_k<<<(n4 + T - 1) / T, T>>>(in_w, p_wi, n4);
        n4 = NLV * DIMV * DIV / 4;
        wcvt_k<<<(n4 + T - 1) / T, T>>>(ow, p_wo, n4);
        n4 = DIMV * DIMV / 4;
        wcvt_k<<<(n4 + T - 1) / T, T>>>(patch_w, p_wp, n4);
    }

    // ---- patch embed ----
    im2col_k<<<EW4, T>>>(x);
    tgemm<true, false, false, false, false><<<dim3(DIMV / 128, MB), GT, SMEMT>>>(
        p_ah, p_wp, patch_b, p_h, nullptr, nullptr, TOKV, DIMV, DIMV);
    addpos_k<<<EW4, T>>>(pos);

    for (int i = 0; i < NLV; i++) {
        // in_proj: A = h fp16 (g_bh); OUT16 -> g_xrh
        tgemm<false, false, false, false, true><<<dim3(2 * DIV / 128, MB), GT, SMEMT>>>(
            p_bh, p_wi + (size_t)i * 2 * DIV * DIMV, nullptr, nullptr,
            p_xrh, nullptr, TOKV, 2 * DIV, DIMV);
        // fused conv+silu + dt/Bp + Ad/Bd
        dtbp_k<<<TOKV / 64, T>>>(
            conv_w + (size_t)i * DIV * 4, conv_b + (size_t)i * DIV,
            dtw + (size_t)i * DSV * DIV, dtb + (size_t)i * DSV,
            xpw + (size_t)i * 2 * DSV * DIV, alog + (size_t)i * DSV);
        scan_k<<<64, 256>>>();
        yg_k<<<EX4, T>>>(Dp + (size_t)i * DIV);
        // out_proj: A = yg fp16 (g_ah); writes h fp32 + h fp16 (g_bh)
        tgemm<false, false, true, false, false><<<dim3(DIMV / 128, MB), GT, SMEMT>>>(
            p_ah, p_wo + (size_t)i * DIMV * DIV, nullptr, p_h,
            p_bh, nullptr, TOKV, DIMV, DIV);

        if (i % 3 == 2) {
            int j = i / 3;
            repack2_k<<<(DIMV * KCAT + T - 1) / T, T>>>(
                kco + (size_t)j * DIMV * DIMV * 8, kbw + (size_t)j * DIMV * DIMV);
            kanA_k<<<EW4, T>>>();
            // combined base+spline GEMM (K=4608) + bias + residual -> h (+ fp16)
            tgemm<true, false, true, true, false><<<dim3(DIMV / 128, MB), GT, SMEMT>>>(
                p_ah, p_wkc, kbi + (size_t)j * DIMV, nullptr,
                p_bh, p_h, TOKV, DIMV, KCAT);
        }
    }

    ln_k<<<TOKV, 256>>>(nw, nb, out);
}

// round 16
// speedup vs baseline: 1.5470x; 1.5470x over previous
#include <cuda_runtime.h>
#include <cuda_fp16.h>
#include <math.h>
#include <stdint.h>

#define DIMV 768
#define NLV 12
#define DSV 16
#define DIV 1536
#define TOKV 8192      // 32 batches * 256 tokens
#define LV 256
#define GSV 5
#define KANK (DIMV * GSV)       // 3840
#define KCAT (KANK + DIMV)      // 4608  (basis | h concat)

// ---------------- scratch (static device globals; no allocation allowed) ----
__device__ float g_h[TOKV * DIMV];                   // running hidden state (fp32)
__device__ float g_Ad[TOKV * DSV];
__device__ float g_Bd[TOKV * DSV];
__device__ float g_ys[TOKV * DSV];
// fp16 activation buffers
__device__ __half g_ah[(size_t)TOKV * KCAT];         // im2col / yg / basis+h concat
__device__ __half g_bh[TOKV * DIMV];                 // h fp16 (GEMM A) — no aliasing
__device__ __half g_xrh[(size_t)TOKV * 2 * DIV];     // in_proj output fp16 (x1|res)
__device__ __half g_x1h[(size_t)TOKV * DIV];         // post conv+silu fp16
// fp16 weight staging
__device__ __half g_wi[(size_t)NLV * 2 * DIV * DIMV];
__device__ __half g_wo[(size_t)NLV * DIMV * DIV];
__device__ __half g_wp[DIMV * DIMV];
__device__ __half g_wkc[(size_t)DIMV * KCAT];        // [wkan | kbw] combined

// ---------------- PTX helpers ----------------------------------------------
__device__ __forceinline__ uint32_t smem_u32(const void* p) {
    uint32_t a;
    asm("{ .reg .u64 t; cvta.to.shared.u64 t, %1; cvt.u32.u64 %0, t; }"
        : "=r"(a) : "l"(p));
    return a;
}
__device__ __forceinline__ void ldsm4(uint32_t& r0, uint32_t& r1,
                                      uint32_t& r2, uint32_t& r3, uint32_t addr)
{
    asm volatile("ldmatrix.sync.aligned.m8n8.x4.shared.b16 {%0,%1,%2,%3}, [%4];"
                 : "=r"(r0), "=r"(r1), "=r"(r2), "=r"(r3) : "r"(addr));
}
__device__ __forceinline__ void mma_f16(float* c, const uint32_t* a, const uint32_t* b)
{
    asm volatile(
        "mma.sync.aligned.m16n8k16.row.col.f32.f16.f16.f32 "
        "{%0,%1,%2,%3}, {%4,%5,%6,%7}, {%8,%9}, {%0,%1,%2,%3};"
        : "+f"(c[0]), "+f"(c[1]), "+f"(c[2]), "+f"(c[3])
        : "r"(a[0]), "r"(a[1]), "r"(a[2]), "r"(a[3]), "r"(b[0]), "r"(b[1]));
}
__device__ __forceinline__ void cp16(uint32_t dst, const void* src)
{
    asm volatile("cp.async.cg.shared.global [%0], [%1], 16;"
                 :: "r"(dst), "l"(src) : "memory");
}
__device__ __forceinline__ void cp_commit()
{
    asm volatile("cp.async.commit_group;" ::: "memory");
}
template<int NN> __device__ __forceinline__ void cp_wait()
{
    asm volatile("cp.async.wait_group %0;" :: "n"(NN) : "memory");
}
__device__ __forceinline__ float h2f(__half h) { return __half2float(h); }

// ---------------- tensor-core GEMM (fp16 single-term mma.sync) --------------
// C[M,N] = A[M,K] @ W[N,K]^T, fp16 operands, fp32 accumulate.
// 128 threads, 4 warps 2x2, warp tile 64x64, CTA tile 128x128, BK=32 fp16,
// 2-stage cp.async, 80B-pitch conflict-free ldmatrix tiles.
// OUT16: fp16 only to Sh. SPLIT: fp16 copy to Sh. HADD: out += H -> H.
#define TILE_B (128 * 80)            // 10240
#define STAGE_B (2 * TILE_B)         // A|W = 20480
#define SMEMT (2 * STAGE_B)          // 40960

template<bool BIAS, bool ACC, bool SPLIT, bool HADD, bool OUT16>
__global__ __launch_bounds__(128, 2)
void tgemm(const __half* __restrict__ A, const __half* __restrict__ W,
           const float* __restrict__ bias, float* __restrict__ C,
           __half* __restrict__ Sh, float* __restrict__ H,
           int M, int N, int K)
{
    extern __shared__ char smem[];
    const uint32_t sb0 = smem_u32(smem);
    const int tid = threadIdx.x, lane = tid & 31, wid = tid >> 5;
    const int row0 = blockIdx.y * 128, col0 = blockIdx.x * 128;
    const int rm = (wid >> 1) * 64, cn = (wid & 1) * 64;

    const __half* gA = A + (size_t)row0 * K;
    const __half* gW = W + (size_t)col0 * K;

    const int lrow = tid >> 2;          // 0..31
    const int lch  = tid & 3;           // 16B chunk 0..3 (8 fp16 each)

    auto issue = [&](int p, int s) {
        const int k0 = p * 32;
        const uint32_t dstb = sb0 + s * STAGE_B;
#pragma unroll
        for (int i = 0; i < 4; i++) {
            int row = lrow + i * 32;
            cp16(dstb + row * 80 + lch * 16,
                 gA + (size_t)row * K + k0 + lch * 8);
        }
#pragma unroll
        for (int i = 0; i < 4; i++) {
            int row = lrow + i * 32;
            cp16(dstb + TILE_B + row * 80 + lch * 16,
                 gW + (size_t)row * K + k0 + lch * 8);
        }
        cp_commit();
    };

    float acc[4][8][4];
#pragma unroll
    for (int a = 0; a < 4; a++)
#pragma unroll
        for (int b = 0; b < 8; b++)
#pragma unroll
            for (int q = 0; q < 4; q++) acc[a][b][q] = 0.f;

    const uint32_t aOff = (uint32_t)(rm + (lane & 15)) * 80 + ((lane >> 4) << 4);
    const uint32_t wOff = (uint32_t)(cn + (lane & 7) + ((lane >> 4) & 1) * 8) * 80
                        + (((lane >> 3) & 1) << 4);

    const int npan = K >> 5;
    issue(0, 0);

    for (int p = 0; p < npan; p++) {
        const bool more = (p + 1 < npan);
        if (more) issue(p + 1, (p + 1) & 1);
        if (more) cp_wait<1>(); else cp_wait<0>();
        __syncthreads();

        const uint32_t sbase = sb0 + (p & 1) * STAGE_B;
#pragma unroll
        for (int ks = 0; ks < 2; ks++) {
            const uint32_t kb = ks * 32;          // 16 fp16 = 32 B
            uint32_t Af[4][4], Wf[8][2];
#pragma unroll
            for (int mt = 0; mt < 4; mt++)
                ldsm4(Af[mt][0], Af[mt][1], Af[mt][2], Af[mt][3],
                      sbase + aOff + mt * 1280 + kb);
#pragma unroll
            for (int bt = 0; bt < 4; bt++) {
                uint32_t r0, r1, r2, r3;
                ldsm4(r0, r1, r2, r3,
                      sbase + TILE_B + wOff + bt * 1280 + kb);
                Wf[bt * 2][0] = r0; Wf[bt * 2][1] = r1;
                Wf[bt * 2 + 1][0] = r2; Wf[bt * 2 + 1][1] = r3;
            }
#pragma unroll
            for (int mt = 0; mt < 4; mt++)
#pragma unroll
                for (int nt = 0; nt < 8; nt++)
                    mma_f16(acc[mt][nt], Af[mt], Wf[nt]);
        }
        __syncthreads();
    }

    // epilogue
#pragma unroll
    for (int mt = 0; mt < 4; mt++) {
#pragma unroll
        for (int nt = 0; nt < 8; nt++) {
            int r = row0 + rm + mt * 16 + (lane >> 2);
            int c = col0 + cn + nt * 8 + (lane & 3) * 2;
            float bx = 0.f, by = 0.f;
            if (BIAS) { bx = bias[c]; by = bias[c + 1]; }
#pragma unroll
            for (int half = 0; half < 2; half++) {
                size_t off = (size_t)(r + half * 8) * N + c;
                float vx = acc[mt][nt][half * 2 + 0] + bx;
                float vy = acc[mt][nt][half * 2 + 1] + by;
                if (OUT16) {
                    *reinterpret_cast<__half2*>(Sh + off) =
                        __floats2half2_rn(vx, vy);
                } else {
                    if (ACC) { vx += C[off]; vy += C[off + 1]; }
                    if (HADD) {
                        vx += H[off]; vy += H[off + 1];
                        *reinterpret_cast<float2*>(H + off) = make_float2(vx, vy);
                    } else {
                        *reinterpret_cast<float2*>(C + off) = make_float2(vx, vy);
                    }
                    if (SPLIT) {
                        *reinterpret_cast<__half2*>(Sh + off) =
                            __floats2half2_rn(vx, vy);
                    }
                }
            }
        }
    }
}

// ---------------- elementwise / small kernels ------------------------------

__global__ void wcvt_k(const float* __restrict__ src, __half* __restrict__ dst, int n4)
{
    int idx = blockIdx.x * blockDim.x + threadIdx.x;
    if (idx >= n4) return;
    float4 v = reinterpret_cast<const float4*>(src)[idx];
    reinterpret_cast<__half2*>(dst)[idx * 2 + 0] = __floats2half2_rn(v.x, v.y);
    reinterpret_cast<__half2*>(dst)[idx * 2 + 1] = __floats2half2_rn(v.z, v.w);
}

__global__ void im2col_k(const float* __restrict__ x)
{
    int idx = blockIdx.x * blockDim.x + threadIdx.x;    // over TOKV*DIMV/4
    if (idx >= TOKV * DIMV / 4) return;
    int col4 = (idx % (DIMV / 4)) * 4;
    int row  = idx / (DIMV / 4);
    int b = row >> 8, t = row & 255;
    int py = t >> 4, px = t & 15;
    int c = col4 >> 8, rj = col4 & 255;
    int r = rj >> 4, s = rj & 15;
    const float4 v = *reinterpret_cast<const float4*>(
        x + (((size_t)(b * 3 + c) * 256) + py * 16 + r) * 256 + px * 16 + s);
    reinterpret_cast<__half2*>(g_ah)[idx * 2 + 0] = __floats2half2_rn(v.x, v.y);
    reinterpret_cast<__half2*>(g_ah)[idx * 2 + 1] = __floats2half2_rn(v.z, v.w);
}

__global__ void addpos_k(const float* __restrict__ pos)
{
    int idx = blockIdx.x * blockDim.x + threadIdx.x;    // over TOKV*DIMV/4
    if (idx >= TOKV * DIMV / 4) return;
    int d4  = idx % (DIMV / 4);
    int row = idx / (DIMV / 4);
    float4 h = reinterpret_cast<const float4*>(g_h)[idx];
    float4 p = reinterpret_cast<const float4*>(pos)[(row & 255) * (DIMV / 4) + d4];
    h.x += p.x; h.y += p.y; h.z += p.z; h.w += p.w;
    reinterpret_cast<float4*>(g_h)[idx] = h;
    reinterpret_cast<__half2*>(g_bh)[idx * 2 + 0] = __floats2half2_rn(h.x, h.y);
    reinterpret_cast<__half2*>(g_bh)[idx * 2 + 1] = __floats2half2_rn(h.z, h.w);
}

// depthwise causal conv (kernel 4) + silu, 4 channels / thread, fp16 in/out
__global__ void conv_silu_k(const float* __restrict__ cw, const float* __restrict__ cb)
{
    int idx = blockIdx.x * blockDim.x + threadIdx.x;    // over TOKV*DIV/4
    if (idx >= TOKV * DIV / 4) return;
    int c4  = (idx % (DIV / 4)) * 4;
    int row = idx / (DIV / 4);
    int l = row & 255;

    float4 a = *reinterpret_cast<const float4*>(cb + c4);
    float4 w0 = *reinterpret_cast<const float4*>(cw + (c4 + 0) * 4);
    float4 w1 = *reinterpret_cast<const float4*>(cw + (c4 + 1) * 4);
    float4 w2 = *reinterpret_cast<const float4*>(cw + (c4 + 2) * 4);
    float4 w3 = *reinterpret_cast<const float4*>(cw + (c4 + 3) * 4);
    const float* wk[4] = { (const float*)&w0, (const float*)&w1,
                           (const float*)&w2, (const float*)&w3 };
#pragma unroll
    for (int k = 0; k < 4; k++) {
        int l2 = l - 3 + k;
        if (l2 >= 0) {
            const __half2* xp = reinterpret_cast<const __half2*>(
                g_xrh + (size_t)(row - 3 + k) * (2 * DIV) + c4);
            float2 x01 = __half22float2(xp[0]);
            float2 x23 = __half22float2(xp[1]);
            a.x = fmaf(x01.x, wk[0][k], a.x);
            a.y = fmaf(x01.y, wk[1][k], a.y);
            a.z = fmaf(x23.x, wk[2][k], a.z);
            a.w = fmaf(x23.y, wk[3][k], a.w);
        }
    }
    a.x = a.x / (1.f + expf(-a.x));
    a.y = a.y / (1.f + expf(-a.y));
    a.z = a.z / (1.f + expf(-a.z));
    a.w = a.w / (1.f + expf(-a.w));
    reinterpret_cast<__half2*>(g_x1h)[idx * 2 + 0] = __floats2half2_rn(a.x, a.y);
    reinterpret_cast<__half2*>(g_x1h)[idx * 2 + 1] = __floats2half2_rn(a.z, a.w);
}

// fused dt + Bp projection + softplus/Ad/Bd (x1 fp16)
__global__ __launch_bounds__(256)
void dtbp_k(const float* __restrict__ dtw, const float* __restrict__ dtb,
            const float* __restrict__ xpw, const float* __restrict__ alog)
{
    __shared__ float Xs[64][36];
    __shared__ float Ws2[32][33];

    const int tid = threadIdx.x;
    const int lane = tid & 31;
    const int wid = tid >> 5;
    const int row0 = blockIdx.x * 64;

    const int xrow = tid >> 3;
    const int xk4  = (tid & 7) * 4;

    float acc[8];
#pragma unroll
    for (int r = 0; r < 8; r++) acc[r] = 0.f;

    const float* wsrc = (xrow < 16)
        ? (dtw + (size_t)xrow * DIV)
        : (xpw + (size_t)xrow * DIV);

    for (int kt = 0; kt < DIV; kt += 32) {
        const __half2* xa = reinterpret_cast<const __half2*>(
            g_x1h + (size_t)(row0 + xrow) * DIV + kt + xk4);
        const __half2* xb = reinterpret_cast<const __half2*>(
            g_x1h + (size_t)(row0 + 32 + xrow) * DIV + kt + xk4);
        float2 a01 = __half22float2(xa[0]), a23 = __half22float2(xa[1]);
        float2 b01 = __half22float2(xb[0]), b23 = __half22float2(xb[1]);
        Xs[xrow][xk4 + 0] = a01.x; Xs[xrow][xk4 + 1] = a01.y;
        Xs[xrow][xk4 + 2] = a23.x; Xs[xrow][xk4 + 3] = a23.y;
        Xs[32 + xrow][xk4 + 0] = b01.x; Xs[32 + xrow][xk4 + 1] = b01.y;
        Xs[32 + xrow][xk4 + 2] = b23.x; Xs[32 + xrow][xk4 + 3] = b23.y;
        float4 wv = *(const float4*)(wsrc + kt + xk4);
        Ws2[xrow][xk4 + 0] = wv.x; Ws2[xrow][xk4 + 1] = wv.y;
        Ws2[xrow][xk4 + 2] = wv.z; Ws2[xrow][xk4 + 3] = wv.w;
        __syncthreads();
#pragma unroll
        for (int kk = 0; kk < 32; kk++) {
            float w = Ws2[lane][kk];
#pragma unroll
            for (int r = 0; r < 8; r++)
                acc[r] = fmaf(Xs[wid * 8 + r][kk], w, acc[r]);
        }
        __syncthreads();
    }

    float dtb_v = (lane < DSV) ? dtb[lane] : 0.f;
    float negA  = (lane < DSV) ? -expf(alog[lane]) : 0.f;

#pragma unroll
    for (int r = 0; r < 8; r++) {
        int row = row0 + wid * 8 + r;
        const __half* xr = g_x1h + (size_t)row * DIV;
        float s = h2f(xr[lane]) + h2f(xr[lane + 32]) + h2f(xr[lane + 64]);
#pragma unroll
        for (int o = 16; o; o >>= 1) s += __shfl_xor_sync(0xffffffffu, s, o);
        float u = s * (1.f / 96.f);
        float bp = __shfl_sync(0xffffffffu, acc[r], (lane & 15) + 16);
        if (lane < DSV) {
            float raw = acc[r] + dtb_v;
            float dtv = fmaxf(raw, 0.f) + log1pf(expf(-fabsf(raw)));
            g_Ad[row * DSV + lane] = expf(negA * dtv);
            g_Bd[row * DSV + lane] = dtv * bp * u;
        }
    }
}

// warp-parallel linear-recurrence scan
__global__ void scan_k()   // <<<64, 256>>> : 512 warps
{
    int g = blockIdx.x * blockDim.x + threadIdx.x;
    int w = g >> 5, lane = g & 31;
    int b = w >> 4, n = w & 15;
    size_t idx0 = (size_t)b * LV * DSV + n + (size_t)(lane * 8) * DSV;

    float a[8], bb[8];
    float A = 1.f, B = 0.f;
#pragma unroll
    for (int i = 0; i < 8; i++) {
        a[i]  = g_Ad[idx0 + (size_t)i * DSV];
        bb[i] = g_Bd[idx0 + (size_t)i * DSV];
        B = B * a[i] + bb[i];
        A = A * a[i];
    }
    float Ai = A, Bi = B;
#pragma unroll
    for (int o = 1; o < 32; o <<= 1) {
        float Ap = __shfl_up_sync(0xffffffffu, Ai, o);
        float Bp = __shfl_up_sync(0xffffffffu, Bi, o);
        if (lane >= o) { Bi = Bp * Ai + Bi; Ai = Ai * Ap; }
    }
    float sin = __shfl_up_sync(0xffffffffu, Bi, 1);
    if (lane == 0) sin = 0.f;
    float s = sin;
#pragma unroll
    for (int i = 0; i < 8; i++) {
        s = s * a[i] + bb[i];
        g_ys[idx0 + (size_t)i * DSV] = s;
    }
}

// gated y -> fp16 into g_ah ([8192,1536] pitch DIV)
__global__ void yg_k(const float* __restrict__ Dp)
{
    int idx = blockIdx.x * blockDim.x + threadIdx.x;    // over TOKV*DIV/4
    if (idx >= TOKV * DIV / 4) return;
    int c4  = (idx % (DIV / 4)) * 4;
    int row = idx / (DIV / 4);
    float ys = g_ys[row * DSV + c4 / 96];
    const __half2* x1p = reinterpret_cast<const __half2*>(g_x1h) + idx * 2;
    float2 x01 = __half22float2(x1p[0]), x23 = __half22float2(x1p[1]);
    float4 dp = *reinterpret_cast<const float4*>(Dp + c4);
    const __half2* rsp = reinterpret_cast<const __half2*>(
        g_xrh + (size_t)row * (2 * DIV) + DIV + c4);
    float2 r01 = __half22float2(rsp[0]), r23 = __half22float2(rsp[1]);
    float ox = (ys + x01.x * dp.x) * (r01.x / (1.f + expf(-r01.x)));
    float oy = (ys + x01.y * dp.y) * (r01.y / (1.f + expf(-r01.y)));
    float oz = (ys + x23.x * dp.z) * (r23.x / (1.f + expf(-r23.x)));
    float ow = (ys + x23.y * dp.w) * (r23.y / (1.f + expf(-r23.y)));
    reinterpret_cast<__half2*>(g_ah)[idx * 2 + 0] = __floats2half2_rn(ox, oy);
    reinterpret_cast<__half2*>(g_ah)[idx * 2 + 1] = __floats2half2_rn(oz, ow);
}

// combined KAN weight: W row o = [ wkan(o, c=ii*5+k) | kbw(o, :) ], K = 4608
__global__ void repack2_k(const float* __restrict__ coeff, const float* __restrict__ kbw)
{
    int idx = blockIdx.x * blockDim.x + threadIdx.x;
    const int TOTAL = DIMV * KCAT;
    if (idx >= TOTAL) return;
    int o = idx / KCAT;
    int c = idx % KCAT;
    float v;
    if (c < KANK)
        v = coeff[((size_t)o * DIMV + c / GSV) * 8 + c % GSV];
    else
        v = kbw[(size_t)o * DIMV + (c - KANK)];
    g_wkc[idx] = __float2half_rn(v);
}

// KAN A build: row = [basis(3840) | h(768)] fp16, pitch KCAT
__global__ void kanA_k()
{
    int idx = blockIdx.x * blockDim.x + threadIdx.x;    // over TOKV*DIMV/4
    if (idx >= TOKV * DIMV / 4) return;
    int d4  = (idx % (DIMV / 4)) * 4;
    int row = idx / (DIMV / 4);
    float4 h = reinterpret_cast<const float4*>(g_h)[idx];
    const float* hv = (const float*)&h;
    size_t rbase = (size_t)row * KCAT;
    __half tmp[20];
    const float inv = 1.f / (0.4f + 1e-8f);
#pragma unroll
    for (int e = 0; e < 4; e++) {
        float xv = hv[e];
#pragma unroll
        for (int k = 0; k < GSV; k++) {
            float gk = -1.f + 0.4f * (float)k;
            float xs = (xv - gk) * inv;
            float v = (xs >= 0.f && xs < 1.f) ? xs : 0.f;
            tmp[e * GSV + k] = __float2half_rn(v);
        }
    }
    uint2* bd = reinterpret_cast<uint2*>(g_ah + rbase + (size_t)d4 * 5);
    const uint2* ts = reinterpret_cast<const uint2*>(tmp);
#pragma unroll
    for (int q = 0; q < 5; q++) bd[q] = ts[q];
    __half2* hd = reinterpret_cast<__half2*>(g_ah + rbase + KANK + d4);
    hd[0] = __floats2half2_rn(h.x, h.y);
    hd[1] = __floats2half2_rn(h.z, h.w);
}

__global__ void ln_k(const float* __restrict__ nw, const float* __restrict__ nb,
                     float* __restrict__ out)
{
    __shared__ float sh[DIMV];
    __shared__ float sbuf[8];
    int row = blockIdx.x;
    int tid = threadIdx.x;
    int lane = tid & 31, w = tid >> 5;

    float s = 0.f;
    for (int d = tid; d < DIMV; d += 256) {
        float v = g_h[(size_t)row * DIMV + d];
        sh[d] = v; s += v;
    }
#pragma unroll
    for (int o = 16; o; o >>= 1) s += __shfl_xor_sync(0xffffffffu, s, o);
    if (lane == 0) sbuf[w] = s;
    __syncthreads();
    if (w == 0) {
        float t = (lane < 8) ? sbuf[lane] : 0.f;
#pragma unroll
        for (int o = 4; o; o >>= 1) t += __shfl_xor_sync(0xffffffffu, t, o);
        if (lane == 0) sbuf[0] = t;
    }
    __syncthreads();
    float mu = sbuf[0] * (1.f / DIMV);
    __syncthreads();

    float s2 = 0.f;
    for (int d = tid; d < DIMV; d += 256) {
        float dv = sh[d] - mu;
        s2 += dv * dv;
    }
#pragma unroll
    for (int o = 16; o; o >>= 1) s2 += __shfl_xor_sync(0xffffffffu, s2, o);
    if (lane == 0) sbuf[w] = s2;
    __syncthreads();
    if (w == 0) {
        float t = (lane < 8) ? sbuf[lane] : 0.f;
#pragma unroll
        for (int o = 4; o; o >>= 1) t += __shfl_xor_sync(0xffffffffu, t, o);
        if (lane == 0) sbuf[0] = t;
    }
    __syncthreads();
    float var = sbuf[0] * (1.f / DIMV);
    float inv = rsqrtf(var + 1e-5f);
    for (int d = tid; d < DIMV; d += 256) {
        out[(size_t)row * DIMV + d] = (sh[d] - mu) * inv * nw[d] + nb[d];
    }
}

// ---------------- host orchestration ---------------------------------------

extern "C" void kernel_launch(void* const* d_in, const int* in_sizes, int n_in,
                              void* d_out, int out_size)
{
    const float* x       = (const float*)d_in[0];
    const float* patch_w = (const float*)d_in[1];
    const float* patch_b = (const float*)d_in[2];
    const float* pos     = (const float*)d_in[3];
    const float* in_w    = (const float*)d_in[4];
    const float* conv_w  = (const float*)d_in[5];
    const float* conv_b  = (const float*)d_in[6];
    const float* xpw     = (const float*)d_in[7];
    const float* dtw     = (const float*)d_in[8];
    const float* dtb     = (const float*)d_in[9];
    const float* alog    = (const float*)d_in[10];
    const float* Dp      = (const float*)d_in[11];
    const float* ow      = (const float*)d_in[12];
    const float* kbw     = (const float*)d_in[13];
    const float* kco     = (const float*)d_in[14];
    const float* kbi     = (const float*)d_in[15];
    const float* nw      = (const float*)d_in[16];
    const float* nb      = (const float*)d_in[17];
    float* out = (float*)d_out;

    cudaFuncSetAttribute(tgemm<false, false, false, false, true >, cudaFuncAttributeMaxDynamicSharedMemorySize, SMEMT);
    cudaFuncSetAttribute(tgemm<false, false, true,  false, false>, cudaFuncAttributeMaxDynamicSharedMemorySize, SMEMT);
    cudaFuncSetAttribute(tgemm<true,  false, false, false, false>, cudaFuncAttributeMaxDynamicSharedMemorySize, SMEMT);
    cudaFuncSetAttribute(tgemm<true,  false, true,  true,  false>, cudaFuncAttributeMaxDynamicSharedMemorySize, SMEMT);

    float *p_h;
    __half *p_ah, *p_bh, *p_xrh, *p_wi, *p_wo, *p_wp, *p_wkc;
    cudaGetSymbolAddress((void**)&p_h,   g_h);
    cudaGetSymbolAddress((void**)&p_ah,  g_ah);
    cudaGetSymbolAddress((void**)&p_bh,  g_bh);
    cudaGetSymbolAddress((void**)&p_xrh, g_xrh);
    cudaGetSymbolAddress((void**)&p_wi,  g_wi);
    cudaGetSymbolAddress((void**)&p_wo,  g_wo);
    cudaGetSymbolAddress((void**)&p_wp,  g_wp);
    cudaGetSymbolAddress((void**)&p_wkc, g_wkc);

    const int T = 256;
    const int GT = 128;          // tgemm threads
    const int MB = TOKV / 128;   // 64
    const int EW4 = (TOKV * DIMV / 4 + T - 1) / T;
    const int EX4 = (TOKV * DIV / 4 + T - 1) / T;

    // ---- weight fp16 conversion ----
    {
        int n4;
        n4 = NLV * 2 * DIV * DIMV / 4;
        wcvt_k<<<(n4 + T - 1) / T, T>>>(in_w, p_wi, n4);
        n4 = NLV * DIMV * DIV / 4;
        wcvt_k<<<(n4 + T - 1) / T, T>>>(ow, p_wo, n4);
        n4 = DIMV * DIMV / 4;
        wcvt_k<<<(n4 + T - 1) / T, T>>>(patch_w, p_wp, n4);
    }

    // ---- patch embed ----
    im2col_k<<<EW4, T>>>(x);
    tgemm<true, false, false, false, false><<<dim3(DIMV / 128, MB), GT, SMEMT>>>(
        p_ah, p_wp, patch_b, p_h, nullptr, nullptr, TOKV, DIMV, DIMV);
    addpos_k<<<EW4, T>>>(pos);

    for (int i = 0; i < NLV; i++) {
        // in_proj: A = h fp16 (g_bh); OUT16 -> g_xrh
        tgemm<false, false, false, false, true><<<dim3(2 * DIV / 128, MB), GT, SMEMT>>>(
            p_bh, p_wi + (size_t)i * 2 * DIV * DIMV, nullptr, nullptr,
            p_xrh, nullptr, TOKV, 2 * DIV, DIMV);
        conv_silu_k<<<EX4, T>>>(
            conv_w + (size_t)i * DIV * 4, conv_b + (size_t)i * DIV);
        dtbp_k<<<TOKV / 64, T>>>(
            dtw + (size_t)i * DSV * DIV, dtb + (size_t)i * DSV,
            xpw + (size_t)i * 2 * DSV * DIV, alog + (size_t)i * DSV);
        scan_k<<<64, 256>>>();
        yg_k<<<EX4, T>>>(Dp + (size_t)i * DIV);
        // out_proj: A = yg fp16 (g_ah); writes h fp32 + h fp16 (g_bh)
        tgemm<false, false, true, false, false><<<dim3(DIMV / 128, MB), GT, SMEMT>>>(
            p_ah, p_wo + (size_t)i * DIMV * DIV, nullptr, p_h,
            p_bh, nullptr, TOKV, DIMV, DIV);

        if (i % 3 == 2) {
            int j = i / 3;
            repack2_k<<<(DIMV * KCAT + T - 1) / T, T>>>(
                kco + (size_t)j * DIMV * DIMV * 8, kbw + (size_t)j * DIMV * DIMV);
            kanA_k<<<EW4, T>>>();
            // combined base+spline GEMM (K=4608) + bias + residual -> h (+ fp16)
            tgemm<true, false, true, true, false><<<dim3(DIMV / 128, MB), GT, SMEMT>>>(
                p_ah, p_wkc, kbi + (size_t)j * DIMV, nullptr,
                p_bh, p_h, TOKV, DIMV, KCAT);
        }
    }

    ln_k<<<TOKV, 256>>>(nw, nb, out);
}

// round 17
// speedup vs baseline: 1.7246x; 1.1148x over previous
#include <cuda_runtime.h>
#include <cuda_fp16.h>
#include <math.h>
#include <stdint.h>

#define DIMV 768
#define NLV 12
#define DSV 16
#define DIV 1536
#define TOKV 8192      // 32 batches * 256 tokens
#define LV 256
#define GSV 5
#define KANK (DIMV * GSV)       // 3840
#define KCAT (KANK + DIMV)      // 4608  (basis | h concat)

// ---------------- scratch (static device globals; no allocation allowed) ----
__device__ float g_h[TOKV * DIMV];                   // running hidden state (fp32)
__device__ float g_Ad[TOKV * DSV];
__device__ float g_Bd[TOKV * DSV];
__device__ float g_ys[TOKV * DSV];
// fp16 activation buffers
__device__ __half g_ah[(size_t)TOKV * KCAT];         // im2col / yg / basis+h concat
__device__ __half g_bh[TOKV * DIMV];                 // h fp16 (GEMM A) — no aliasing
__device__ __half g_xrh[(size_t)TOKV * 2 * DIV];     // in_proj output fp16 (x1|res)
__device__ __half g_x1h[(size_t)TOKV * DIV];         // post conv+silu fp16
// fp16 weight staging
__device__ __half g_wi[(size_t)NLV * 2 * DIV * DIMV];
__device__ __half g_wo[(size_t)NLV * DIMV * DIV];
__device__ __half g_wp[DIMV * DIMV];
__device__ __half g_wkc[(size_t)DIMV * KCAT];        // [wkan | kbw] combined

// ---------------- PTX helpers ----------------------------------------------
__device__ __forceinline__ uint32_t smem_u32(const void* p) {
    uint32_t a;
    asm("{ .reg .u64 t; cvta.to.shared.u64 t, %1; cvt.u32.u64 %0, t; }"
        : "=r"(a) : "l"(p));
    return a;
}
__device__ __forceinline__ void ldsm4(uint32_t& r0, uint32_t& r1,
                                      uint32_t& r2, uint32_t& r3, uint32_t addr)
{
    asm volatile("ldmatrix.sync.aligned.m8n8.x4.shared.b16 {%0,%1,%2,%3}, [%4];"
                 : "=r"(r0), "=r"(r1), "=r"(r2), "=r"(r3) : "r"(addr));
}
__device__ __forceinline__ void mma_f16(float* c, const uint32_t* a, const uint32_t* b)
{
    asm volatile(
        "mma.sync.aligned.m16n8k16.row.col.f32.f16.f16.f32 "
        "{%0,%1,%2,%3}, {%4,%5,%6,%7}, {%8,%9}, {%0,%1,%2,%3};"
        : "+f"(c[0]), "+f"(c[1]), "+f"(c[2]), "+f"(c[3])
        : "r"(a[0]), "r"(a[1]), "r"(a[2]), "r"(a[3]), "r"(b[0]), "r"(b[1]));
}
__device__ __forceinline__ void cp16(uint32_t dst, const void* src)
{
    asm volatile("cp.async.cg.shared.global [%0], [%1], 16;"
                 :: "r"(dst), "l"(src) : "memory");
}
__device__ __forceinline__ void cp_commit()
{
    asm volatile("cp.async.commit_group;" ::: "memory");
}
template<int NN> __device__ __forceinline__ void cp_wait()
{
    asm volatile("cp.async.wait_group %0;" :: "n"(NN) : "memory");
}
__device__ __forceinline__ float h2f(__half h) { return __half2float(h); }

// ---------------- tensor-core GEMM (fp16 single-term mma.sync) --------------
#define TILE_B (128 * 80)            // 10240
#define STAGE_B (2 * TILE_B)         // A|W = 20480
#define SMEMT (2 * STAGE_B)          // 40960

template<bool BIAS, bool ACC, bool SPLIT, bool HADD, bool OUT16>
__global__ __launch_bounds__(128, 2)
void tgemm(const __half* __restrict__ A, const __half* __restrict__ W,
           const float* __restrict__ bias, float* __restrict__ C,
           __half* __restrict__ Sh, float* __restrict__ H,
           int M, int N, int K)
{
    extern __shared__ char smem[];
    const uint32_t sb0 = smem_u32(smem);
    const int tid = threadIdx.x, lane = tid & 31, wid = tid >> 5;
    const int row0 = blockIdx.y * 128, col0 = blockIdx.x * 128;
    const int rm = (wid >> 1) * 64, cn = (wid & 1) * 64;

    const __half* gA = A + (size_t)row0 * K;
    const __half* gW = W + (size_t)col0 * K;

    const int lrow = tid >> 2;          // 0..31
    const int lch  = tid & 3;           // 16B chunk 0..3 (8 fp16 each)

    auto issue = [&](int p, int s) {
        const int k0 = p * 32;
        const uint32_t dstb = sb0 + s * STAGE_B;
#pragma unroll
        for (int i = 0; i < 4; i++) {
            int row = lrow + i * 32;
            cp16(dstb + row * 80 + lch * 16,
                 gA + (size_t)row * K + k0 + lch * 8);
        }
#pragma unroll
        for (int i = 0; i < 4; i++) {
            int row = lrow + i * 32;
            cp16(dstb + TILE_B + row * 80 + lch * 16,
                 gW + (size_t)row * K + k0 + lch * 8);
        }
        cp_commit();
    };

    float acc[4][8][4];
#pragma unroll
    for (int a = 0; a < 4; a++)
#pragma unroll
        for (int b = 0; b < 8; b++)
#pragma unroll
            for (int q = 0; q < 4; q++) acc[a][b][q] = 0.f;

    const uint32_t aOff = (uint32_t)(rm + (lane & 15)) * 80 + ((lane >> 4) << 4);
    const uint32_t wOff = (uint32_t)(cn + (lane & 7) + ((lane >> 4) & 1) * 8) * 80
                        + (((lane >> 3) & 1) << 4);

    const int npan = K >> 5;
    issue(0, 0);

    for (int p = 0; p < npan; p++) {
        const bool more = (p + 1 < npan);
        if (more) issue(p + 1, (p + 1) & 1);
        if (more) cp_wait<1>(); else cp_wait<0>();
        __syncthreads();

        const uint32_t sbase = sb0 + (p & 1) * STAGE_B;
#pragma unroll
        for (int ks = 0; ks < 2; ks++) {
            const uint32_t kb = ks * 32;          // 16 fp16 = 32 B
            uint32_t Af[4][4], Wf[8][2];
#pragma unroll
            for (int mt = 0; mt < 4; mt++)
                ldsm4(Af[mt][0], Af[mt][1], Af[mt][2], Af[mt][3],
                      sbase + aOff + mt * 1280 + kb);
#pragma unroll
            for (int bt = 0; bt < 4; bt++) {
                uint32_t r0, r1, r2, r3;
                ldsm4(r0, r1, r2, r3,
                      sbase + TILE_B + wOff + bt * 1280 + kb);
                Wf[bt * 2][0] = r0; Wf[bt * 2][1] = r1;
                Wf[bt * 2 + 1][0] = r2; Wf[bt * 2 + 1][1] = r3;
            }
#pragma unroll
            for (int mt = 0; mt < 4; mt++)
#pragma unroll
                for (int nt = 0; nt < 8; nt++)
                    mma_f16(acc[mt][nt], Af[mt], Wf[nt]);
        }
        __syncthreads();
    }

    // epilogue
#pragma unroll
    for (int mt = 0; mt < 4; mt++) {
#pragma unroll
        for (int nt = 0; nt < 8; nt++) {
            int r = row0 + rm + mt * 16 + (lane >> 2);
            int c = col0 + cn + nt * 8 + (lane & 3) * 2;
            float bx = 0.f, by = 0.f;
            if (BIAS) { bx = bias[c]; by = bias[c + 1]; }
#pragma unroll
            for (int half = 0; half < 2; half++) {
                size_t off = (size_t)(r + half * 8) * N + c;
                float vx = acc[mt][nt][half * 2 + 0] + bx;
                float vy = acc[mt][nt][half * 2 + 1] + by;
                if (OUT16) {
                    *reinterpret_cast<__half2*>(Sh + off) =
                        __floats2half2_rn(vx, vy);
                } else {
                    if (ACC) { vx += C[off]; vy += C[off + 1]; }
                    if (HADD) {
                        vx += H[off]; vy += H[off + 1];
                        *reinterpret_cast<float2*>(H + off) = make_float2(vx, vy);
                    } else {
                        *reinterpret_cast<float2*>(C + off) = make_float2(vx, vy);
                    }
                    if (SPLIT) {
                        *reinterpret_cast<__half2*>(Sh + off) =
                            __floats2half2_rn(vx, vy);
                    }
                }
            }
        }
    }
}

// ---------------- elementwise / small kernels ------------------------------

__global__ void wcvt_k(const float* __restrict__ src, __half* __restrict__ dst, int n4)
{
    int idx = blockIdx.x * blockDim.x + threadIdx.x;
    if (idx >= n4) return;
    float4 v = reinterpret_cast<const float4*>(src)[idx];
    reinterpret_cast<__half2*>(dst)[idx * 2 + 0] = __floats2half2_rn(v.x, v.y);
    reinterpret_cast<__half2*>(dst)[idx * 2 + 1] = __floats2half2_rn(v.z, v.w);
}

__global__ void im2col_k(const float* __restrict__ x)
{
    int idx = blockIdx.x * blockDim.x + threadIdx.x;    // over TOKV*DIMV/4
    if (idx >= TOKV * DIMV / 4) return;
    int col4 = (idx % (DIMV / 4)) * 4;
    int row  = idx / (DIMV / 4);
    int b = row >> 8, t = row & 255;
    int py = t >> 4, px = t & 15;
    int c = col4 >> 8, rj = col4 & 255;
    int r = rj >> 4, s = rj & 15;
    const float4 v = *reinterpret_cast<const float4*>(
        x + (((size_t)(b * 3 + c) * 256) + py * 16 + r) * 256 + px * 16 + s);
    reinterpret_cast<__half2*>(g_ah)[idx * 2 + 0] = __floats2half2_rn(v.x, v.y);
    reinterpret_cast<__half2*>(g_ah)[idx * 2 + 1] = __floats2half2_rn(v.z, v.w);
}

__global__ void addpos_k(const float* __restrict__ pos)
{
    int idx = blockIdx.x * blockDim.x + threadIdx.x;    // over TOKV*DIMV/4
    if (idx >= TOKV * DIMV / 4) return;
    int d4  = idx % (DIMV / 4);
    int row = idx / (DIMV / 4);
    float4 h = reinterpret_cast<const float4*>(g_h)[idx];
    float4 p = reinterpret_cast<const float4*>(pos)[(row & 255) * (DIMV / 4) + d4];
    h.x += p.x; h.y += p.y; h.z += p.z; h.w += p.w;
    reinterpret_cast<float4*>(g_h)[idx] = h;
    reinterpret_cast<__half2*>(g_bh)[idx * 2 + 0] = __floats2half2_rn(h.x, h.y);
    reinterpret_cast<__half2*>(g_bh)[idx * 2 + 1] = __floats2half2_rn(h.z, h.w);
}

// smem-tiled depthwise causal conv(4)+silu.
// Block: 64 tokens x 64 channels. Input tile (64+3) x 64 staged in smem once.
// Grid: (DIV/64, TOKV/64) = (24, 128). Blocks never straddle a 256-seq.
__global__ __launch_bounds__(256)
void conv_silu_k(const float* __restrict__ cw, const float* __restrict__ cb)
{
    __shared__ __half2 sx[67][32];      // [token+3][ch pair]
    __shared__ float scw[64][4];
    __shared__ float scb[64];

    const int tid = threadIdx.x;
    const int c0   = blockIdx.x * 64;
    const int row0 = blockIdx.y * 64;
    const int l0   = row0 & 255;        // 0,64,128,192

    // stage conv weights/bias
    if (tid < 64) {
        float4 w = *reinterpret_cast<const float4*>(cw + (c0 + tid) * 4);
        scw[tid][0] = w.x; scw[tid][1] = w.y; scw[tid][2] = w.z; scw[tid][3] = w.w;
        scb[tid] = cb[c0 + tid];
    }
    // stage input tile: rows -3..63 (zero before sequence start)
    for (int i = tid; i < 67 * 32; i += 256) {
        int t = i / 32 - 3;             // -3..63
        int ch2 = i % 32;
        __half2 v = __floats2half2_rn(0.f, 0.f);
        if (t >= 0 || l0 > 0)
            v = *reinterpret_cast<const __half2*>(
                g_xrh + (size_t)(row0 + t) * (2 * DIV) + c0 + ch2 * 2);
        sx[t + 3][ch2] = v;
    }
    __syncthreads();

    // compute: 64 tokens x 32 pairs = 2048 outputs / 256 threads = 8 each
    for (int i = tid; i < 64 * 32; i += 256) {
        int t = i / 32, ch2 = i % 32;
        int cc = ch2 * 2;
        float ax = scb[cc], ay = scb[cc + 1];
#pragma unroll
        for (int k = 0; k < 4; k++) {
            float2 xv = __half22float2(sx[t + k][ch2]);
            ax = fmaf(xv.x, scw[cc][k], ax);
            ay = fmaf(xv.y, scw[cc + 1][k], ay);
        }
        ax = ax / (1.f + expf(-ax));
        ay = ay / (1.f + expf(-ay));
        *reinterpret_cast<__half2*>(
            g_x1h + (size_t)(row0 + t) * DIV + c0 + cc) = __floats2half2_rn(ax, ay);
    }
}

// fused dt + Bp projection + softplus/Ad/Bd (x1 fp16), 32 rows / block
__global__ __launch_bounds__(256)
void dtbp_k(const float* __restrict__ dtw, const float* __restrict__ dtb,
            const float* __restrict__ xpw, const float* __restrict__ alog)
{
    __shared__ float Xs[32][36];
    __shared__ float Ws2[32][33];

    const int tid = threadIdx.x;
    const int lane = tid & 31;
    const int wid = tid >> 5;           // 0..7 (4 rows each)
    const int row0 = blockIdx.x * 32;

    const int xrow = tid >> 3;          // 0..31
    const int xk4  = (tid & 7) * 4;

    float acc[4];
#pragma unroll
    for (int r = 0; r < 4; r++) acc[r] = 0.f;

    const float* wsrc = (xrow < 16)
        ? (dtw + (size_t)xrow * DIV)
        : (xpw + (size_t)xrow * DIV);

    for (int kt = 0; kt < DIV; kt += 32) {
        const __half2* xa = reinterpret_cast<const __half2*>(
            g_x1h + (size_t)(row0 + xrow) * DIV + kt + xk4);
        float2 a01 = __half22float2(xa[0]), a23 = __half22float2(xa[1]);
        Xs[xrow][xk4 + 0] = a01.x; Xs[xrow][xk4 + 1] = a01.y;
        Xs[xrow][xk4 + 2] = a23.x; Xs[xrow][xk4 + 3] = a23.y;
        float4 wv = *(const float4*)(wsrc + kt + xk4);
        Ws2[xrow][xk4 + 0] = wv.x; Ws2[xrow][xk4 + 1] = wv.y;
        Ws2[xrow][xk4 + 2] = wv.z; Ws2[xrow][xk4 + 3] = wv.w;
        __syncthreads();
#pragma unroll
        for (int kk = 0; kk < 32; kk++) {
            float w = Ws2[lane][kk];
#pragma unroll
            for (int r = 0; r < 4; r++)
                acc[r] = fmaf(Xs[wid * 4 + r][kk], w, acc[r]);
        }
        __syncthreads();
    }

    float dtb_v = (lane < DSV) ? dtb[lane] : 0.f;
    float negA  = (lane < DSV) ? -expf(alog[lane]) : 0.f;

#pragma unroll
    for (int r = 0; r < 4; r++) {
        int row = row0 + wid * 4 + r;
        const __half* xr = g_x1h + (size_t)row * DIV;
        float s = h2f(xr[lane]) + h2f(xr[lane + 32]) + h2f(xr[lane + 64]);
#pragma unroll
        for (int o = 16; o; o >>= 1) s += __shfl_xor_sync(0xffffffffu, s, o);
        float u = s * (1.f / 96.f);
        float bp = __shfl_sync(0xffffffffu, acc[r], (lane & 15) + 16);
        if (lane < DSV) {
            float raw = acc[r] + dtb_v;
            float dtv = fmaxf(raw, 0.f) + log1pf(expf(-fabsf(raw)));
            g_Ad[row * DSV + lane] = expf(negA * dtv);
            g_Bd[row * DSV + lane] = dtv * bp * u;
        }
    }
}

// warp-parallel linear-recurrence scan
__global__ void scan_k()   // <<<64, 256>>> : 512 warps
{
    int g = blockIdx.x * blockDim.x + threadIdx.x;
    int w = g >> 5, lane = g & 31;
    int b = w >> 4, n = w & 15;
    size_t idx0 = (size_t)b * LV * DSV + n + (size_t)(lane * 8) * DSV;

    float a[8], bb[8];
    float A = 1.f, B = 0.f;
#pragma unroll
    for (int i = 0; i < 8; i++) {
        a[i]  = g_Ad[idx0 + (size_t)i * DSV];
        bb[i] = g_Bd[idx0 + (size_t)i * DSV];
        B = B * a[i] + bb[i];
        A = A * a[i];
    }
    float Ai = A, Bi = B;
#pragma unroll
    for (int o = 1; o < 32; o <<= 1) {
        float Ap = __shfl_up_sync(0xffffffffu, Ai, o);
        float Bp = __shfl_up_sync(0xffffffffu, Bi, o);
        if (lane >= o) { Bi = Bp * Ai + Bi; Ai = Ai * Ap; }
    }
    float sin = __shfl_up_sync(0xffffffffu, Bi, 1);
    if (lane == 0) sin = 0.f;
    float s = sin;
#pragma unroll
    for (int i = 0; i < 8; i++) {
        s = s * a[i] + bb[i];
        g_ys[idx0 + (size_t)i * DSV] = s;
    }
}

// gated y -> fp16 into g_ah ([8192,1536] pitch DIV)
__global__ void yg_k(const float* __restrict__ Dp)
{
    int idx = blockIdx.x * blockDim.x + threadIdx.x;    // over TOKV*DIV/4
    if (idx >= TOKV * DIV / 4) return;
    int c4  = (idx % (DIV / 4)) * 4;
    int row = idx / (DIV / 4);
    float ys = g_ys[row * DSV + c4 / 96];
    const __half2* x1p = reinterpret_cast<const __half2*>(g_x1h) + idx * 2;
    float2 x01 = __half22float2(x1p[0]), x23 = __half22float2(x1p[1]);
    float4 dp = *reinterpret_cast<const float4*>(Dp + c4);
    const __half2* rsp = reinterpret_cast<const __half2*>(
        g_xrh + (size_t)row * (2 * DIV) + DIV + c4);
    float2 r01 = __half22float2(rsp[0]), r23 = __half22float2(rsp[1]);
    float ox = (ys + x01.x * dp.x) * (r01.x / (1.f + expf(-r01.x)));
    float oy = (ys + x01.y * dp.y) * (r01.y / (1.f + expf(-r01.y)));
    float oz = (ys + x23.x * dp.z) * (r23.x / (1.f + expf(-r23.x)));
    float ow = (ys + x23.y * dp.w) * (r23.y / (1.f + expf(-r23.y)));
    reinterpret_cast<__half2*>(g_ah)[idx * 2 + 0] = __floats2half2_rn(ox, oy);
    reinterpret_cast<__half2*>(g_ah)[idx * 2 + 1] = __floats2half2_rn(oz, ow);
}

// combined KAN weight: W row o = [ wkan(o, c=ii*5+k) | kbw(o, :) ], K = 4608
__global__ void repack2_k(const float* __restrict__ coeff, const float* __restrict__ kbw)
{
    int idx = blockIdx.x * blockDim.x + threadIdx.x;
    const int TOTAL = DIMV * KCAT;
    if (idx >= TOTAL) return;
    int o = idx / KCAT;
    int c = idx % KCAT;
    float v;
    if (c < KANK)
        v = coeff[((size_t)o * DIMV + c / GSV) * 8 + c % GSV];
    else
        v = kbw[(size_t)o * DIMV + (c - KANK)];
    g_wkc[idx] = __float2half_rn(v);
}

// KAN A build: row = [basis(3840) | h(768)] fp16, pitch KCAT
__global__ void kanA_k()
{
    int idx = blockIdx.x * blockDim.x + threadIdx.x;    // over TOKV*DIMV/4
    if (idx >= TOKV * DIMV / 4) return;
    int d4  = (idx % (DIMV / 4)) * 4;
    int row = idx / (DIMV / 4);
    float4 h = reinterpret_cast<const float4*>(g_h)[idx];
    const float* hv = (const float*)&h;
    size_t rbase = (size_t)row * KCAT;
    __half tmp[20];
    const float inv = 1.f / (0.4f + 1e-8f);
#pragma unroll
    for (int e = 0; e < 4; e++) {
        float xv = hv[e];
#pragma unroll
        for (int k = 0; k < GSV; k++) {
            float gk = -1.f + 0.4f * (float)k;
            float xs = (xv - gk) * inv;
            float v = (xs >= 0.f && xs < 1.f) ? xs : 0.f;
            tmp[e * GSV + k] = __float2half_rn(v);
        }
    }
    uint2* bd = reinterpret_cast<uint2*>(g_ah + rbase + (size_t)d4 * 5);
    const uint2* ts = reinterpret_cast<const uint2*>(tmp);
#pragma unroll
    for (int q = 0; q < 5; q++) bd[q] = ts[q];
    __half2* hd = reinterpret_cast<__half2*>(g_ah + rbase + KANK + d4);
    hd[0] = __floats2half2_rn(h.x, h.y);
    hd[1] = __floats2half2_rn(h.z, h.w);
}

__global__ void ln_k(const float* __restrict__ nw, const float* __restrict__ nb,
                     float* __restrict__ out)
{
    __shared__ float sh[DIMV];
    __shared__ float sbuf[8];
    int row = blockIdx.x;
    int tid = threadIdx.x;
    int lane = tid & 31, w = tid >> 5;

    float s = 0.f;
    for (int d = tid; d < DIMV; d += 256) {
        float v = g_h[(size_t)row * DIMV + d];
        sh[d] = v; s += v;
    }
#pragma unroll
    for (int o = 16; o; o >>= 1) s += __shfl_xor_sync(0xffffffffu, s, o);
    if (lane == 0) sbuf[w] = s;
    __syncthreads();
    if (w == 0) {
        float t = (lane < 8) ? sbuf[lane] : 0.f;
#pragma unroll
        for (int o = 4; o; o >>= 1) t += __shfl_xor_sync(0xffffffffu, t, o);
        if (lane == 0) sbuf[0] = t;
    }
    __syncthreads();
    float mu = sbuf[0] * (1.f / DIMV);
    __syncthreads();

    float s2 = 0.f;
    for (int d = tid; d < DIMV; d += 256) {
        float dv = sh[d] - mu;
        s2 += dv * dv;
    }
#pragma unroll
    for (int o = 16; o; o >>= 1) s2 += __shfl_xor_sync(0xffffffffu, s2, o);
    if (lane == 0) sbuf[w] = s2;
    __syncthreads();
    if (w == 0) {
        float t = (lane < 8) ? sbuf[lane] : 0.f;
#pragma unroll
        for (int o = 4; o; o >>= 1) t += __shfl_xor_sync(0xffffffffu, t, o);
        if (lane == 0) sbuf[0] = t;
    }
    __syncthreads();
    float var = sbuf[0] * (1.f / DIMV);
    float inv = rsqrtf(var + 1e-5f);
    for (int d = tid; d < DIMV; d += 256) {
        out[(size_t)row * DIMV + d] = (sh[d] - mu) * inv * nw[d] + nb[d];
    }
}

// ---------------- host orchestration ---------------------------------------

extern "C" void kernel_launch(void* const* d_in, const int* in_sizes, int n_in,
                              void* d_out, int out_size)
{
    const float* x       = (const float*)d_in[0];
    const float* patch_w = (const float*)d_in[1];
    const float* patch_b = (const float*)d_in[2];
    const float* pos     = (const float*)d_in[3];
    const float* in_w    = (const float*)d_in[4];
    const float* conv_w  = (const float*)d_in[5];
    const float* conv_b  = (const float*)d_in[6];
    const float* xpw     = (const float*)d_in[7];
    const float* dtw     = (const float*)d_in[8];
    const float* dtb     = (const float*)d_in[9];
    const float* alog    = (const float*)d_in[10];
    const float* Dp      = (const float*)d_in[11];
    const float* ow      = (const float*)d_in[12];
    const float* kbw     = (const float*)d_in[13];
    const float* kco     = (const float*)d_in[14];
    const float* kbi     = (const float*)d_in[15];
    const float* nw      = (const float*)d_in[16];
    const float* nb      = (const float*)d_in[17];
    float* out = (float*)d_out;

    cudaFuncSetAttribute(tgemm<false, false, false, false, true >, cudaFuncAttributeMaxDynamicSharedMemorySize, SMEMT);
    cudaFuncSetAttribute(tgemm<false, false, true,  false, false>, cudaFuncAttributeMaxDynamicSharedMemorySize, SMEMT);
    cudaFuncSetAttribute(tgemm<true,  false, false, false, false>, cudaFuncAttributeMaxDynamicSharedMemorySize, SMEMT);
    cudaFuncSetAttribute(tgemm<true,  false, true,  true,  false>, cudaFuncAttributeMaxDynamicSharedMemorySize, SMEMT);

    float *p_h;
    __half *p_ah, *p_bh, *p_xrh, *p_wi, *p_wo, *p_wp, *p_wkc;
    cudaGetSymbolAddress((void**)&p_h,   g_h);
    cudaGetSymbolAddress((void**)&p_ah,  g_ah);
    cudaGetSymbolAddress((void**)&p_bh,  g_bh);
    cudaGetSymbolAddress((void**)&p_xrh, g_xrh);
    cudaGetSymbolAddress((void**)&p_wi,  g_wi);
    cudaGetSymbolAddress((void**)&p_wo,  g_wo);
    cudaGetSymbolAddress((void**)&p_wp,  g_wp);
    cudaGetSymbolAddress((void**)&p_wkc, g_wkc);

    const int T = 256;
    const int GT = 128;          // tgemm threads
    const int MB = TOKV / 128;   // 64
    const int EW4 = (TOKV * DIMV / 4 + T - 1) / T;

    // ---- weight fp16 conversion ----
    {
        int n4;
        n4 = NLV * 2 * DIV * DIMV / 4;
        wcvt_k<<<(n4 + T - 1) / T, T>>>(in_w, p_wi, n4);
        n4 = NLV * DIMV * DIV / 4;
        wcvt_k<<<(n4 + T - 1) / T, T>>>(ow, p_wo, n4);
        n4 = DIMV * DIMV / 4;
        wcvt_k<<<(n4 + T - 1) / T, T>>>(patch_w, p_wp, n4);
    }

    // ---- patch embed ----
    im2col_k<<<EW4, T>>>(x);
    tgemm<true, false, false, false, false><<<dim3(DIMV / 128, MB), GT, SMEMT>>>(
        p_ah, p_wp, patch_b, p_h, nullptr, nullptr, TOKV, DIMV, DIMV);
    addpos_k<<<EW4, T>>>(pos);

    for (int i = 0; i < NLV; i++) {
        // in_proj: A = h fp16 (g_bh); OUT16 -> g_xrh
        tgemm<false, false, false, false, true><<<dim3(2 * DIV / 128, MB), GT, SMEMT>>>(
            p_bh, p_wi + (size_t)i * 2 * DIV * DIMV, nullptr, nullptr,
            p_xrh, nullptr, TOKV, 2 * DIV, DIMV);
        conv_silu_k<<<dim3(DIV / 64, TOKV / 64), T>>>(
            conv_w + (size_t)i * DIV * 4, conv_b + (size_t)i * DIV);
        dtbp_k<<<TOKV / 32, T>>>(
            dtw + (size_t)i * DSV * DIV, dtb + (size_t)i * DSV,
            xpw + (size_t)i * 2 * DSV * DIV, alog + (size_t)i * DSV);
        scan_k<<<64, 256>>>();
        yg_k<<<(TOKV * DIV / 4 + T - 1) / T, T>>>(Dp + (size_t)i * DIV);
        // out_proj: A = yg fp16 (g_ah); writes h fp32 + h fp16 (g_bh)
        tgemm<false, false, true, false, false><<<dim3(DIMV / 128, MB), GT, SMEMT>>>(
            p_ah, p_wo + (size_t)i * DIMV * DIV, nullptr, p_h,
            p_bh, nullptr, TOKV, DIMV, DIV);

        if (i % 3 == 2) {
            int j = i / 3;
            repack2_k<<<(DIMV * KCAT + T - 1) / T, T>>>(
                kco + (size_t)j * DIMV * DIMV * 8, kbw + (size_t)j * DIMV * DIMV);
            kanA_k<<<EW4, T>>>();
            // combined base+spline GEMM (K=4608) + bias + residual -> h (+ fp16)
            tgemm<true, false, true, true, false><<<dim3(DIMV / 128, MB), GT, SMEMT>>>(
                p_ah, p_wkc, kbi + (size_t)j * DIMV, nullptr,
                p_bh, p_h, TOKV, DIMV, KCAT);
        }
    }

    ln_k<<<TOKV, 256>>>(nw, nb, out);
}